// round 16
// baseline (speedup 1.0000x reference)
#include <cuda_runtime.h>
#include <cuda_fp16.h>
#include <cstdint>

#define NN 2048
#define NT 10
#define KK 5
constexpr float LN_EPS = 1e-5f;

// GEMM tiling: CTA 128x128, BK=64, 4 warps (2x2), warp tile 64x64, 3 stages
// rotating across tiles. 296 persistent CTAs (2/SM), strided tile loop with
// cross-tile prologue prefetch under the epilogue.
#define BM 128
#define BN 128
#define BK 64
#define KCH (NN / BK)                          // 32
#define STAGE_BYTES (BM * 128 + BK * 256)      // A 16KB + B 16KB = 32KB
#define SMEM_DYN (3 * STAGE_BYTES + 1024)      // 99328
#define TILES_PER_T 256                        // 16x16
#define TILES_PER_PHASE (NT * TILES_PER_T)     // 2560
#define TOT_TILES (3 * TILES_PER_PHASE)        // 7680
#define GRID_P 296                             // 2 x 148 SMs (safe on >=148)

// Scratch (__device__ globals; allocation-free rule)
__device__ __half g_Gh [(size_t)NT * NN * NN];  // G_norm
__device__ __half g_G2h[(size_t)NT * NN * NN];  // G^2
__device__ __half g_G3h[(size_t)NT * NN * NN];  // G^3
__device__ __half g_Qh [(size_t)NT * NN * NN];  // Q = a5 G^2 + a4 G + a3 I
__device__ float  g_acc[(size_t)NT * NN * NN];  // pre-LN accumulator (fp32)
__device__ float  g_coef[NT][6];
__device__ int    g_done[2][NT];                // tile-completion counters

__device__ __forceinline__ float clip01(float v) { return fminf(fmaxf(v, 0.f), 1.f); }

__device__ __forceinline__ void cpasync16(uint32_t s, const void* g) {
    asm volatile("cp.async.cg.shared.global [%0], [%1], 16;\n" :: "r"(s), "l"(g));
}
__device__ __forceinline__ void ldsm4(uint32_t* r, uint32_t addr) {
    asm volatile("ldmatrix.sync.aligned.m8n8.x4.shared.b16 {%0,%1,%2,%3}, [%4];"
                 : "=r"(r[0]), "=r"(r[1]), "=r"(r[2]), "=r"(r[3]) : "r"(addr));
}
__device__ __forceinline__ void ldsm4t(uint32_t* r, uint32_t addr) {
    asm volatile("ldmatrix.sync.aligned.m8n8.x4.trans.shared.b16 {%0,%1,%2,%3}, [%4];"
                 : "=r"(r[0]), "=r"(r[1]), "=r"(r[2]), "=r"(r[3]) : "r"(addr));
}
__device__ __forceinline__ void mma16816(float* c, const uint32_t* a,
                                         uint32_t b0, uint32_t b1) {
    asm volatile("mma.sync.aligned.m16n8k16.row.col.f32.f16.f16.f32 "
                 "{%0,%1,%2,%3}, {%4,%5,%6,%7}, {%8,%9}, {%0,%1,%2,%3};"
                 : "+f"(c[0]), "+f"(c[1]), "+f"(c[2]), "+f"(c[3])
                 : "r"(a[0]), "r"(a[1]), "r"(a[2]), "r"(a[3]), "r"(b0), "r"(b1));
}

struct TileInfo {
    int phase, t, m0, n0;
    const __half *A, *B;
    size_t baseT;
};
__device__ __forceinline__ TileInfo decode_tile(int idx) {
    TileInfo ti;
    ti.phase = idx / TILES_PER_PHASE;
    int rem = idx - ti.phase * TILES_PER_PHASE;
    ti.t = rem / TILES_PER_T;
    int tile = rem - ti.t * TILES_PER_T;
    ti.m0 = (tile >> 4) * BM;
    ti.n0 = (tile & 15) * BN;
    ti.baseT = (size_t)ti.t * NN * NN;
    if (ti.phase == 0)      { ti.A = g_Gh;  ti.B = g_Gh;  }
    else if (ti.phase == 1) { ti.A = g_G2h; ti.B = g_Gh;  }
    else                    { ti.A = g_Qh;  ti.B = g_G3h; }
    return ti;
}

// -------------------------------------------------------------------------
// prep: per (t,i) row — degree + row-normalize -> g_Gh (fp16).
// Block 0 also computes the polynomial coefficients and zeroes counters.
// -------------------------------------------------------------------------
__global__ __launch_bounds__(256) void prep_kernel(const float* __restrict__ x,
                                                   const float* __restrict__ w) {
    if (blockIdx.x == 0) {
        int id = threadIdx.x;
        if (id < 2 * NT) ((int*)g_done)[id] = 0;
        if (id < NT) {
            int t = id;
            float c[6] = {1.f, 0.f, 0.f, 0.f, 0.f, 0.f};
            float a[6] = {0.f, 0.f, 0.f, 0.f, 0.f, 0.f};
            for (int k = 0; k < KK; k++) {
                float wk = clip01(w[t * KK + k]);
                float nc[6];
                nc[0] = 1.f - wk;
#pragma unroll
                for (int m = 1; m < 6; m++) nc[m] = wk * c[m - 1];
#pragma unroll
                for (int m = 0; m < 6; m++) { c[m] = nc[m]; a[m] += nc[m]; }
            }
#pragma unroll
            for (int m = 0; m < 6; m++) g_coef[t][m] = a[m];
        }
    }

    int row = blockIdx.x;
    int t = row / NN, i = row - t * NN;
    const float4* xr = reinterpret_cast<const float4*>(x + ((size_t)i * NT + t) * NN);

    float4 v[2];
    float s = 0.f;
#pragma unroll
    for (int q = 0; q < 2; q++) {
        v[q] = xr[threadIdx.x + q * 256];
        s += v[q].x + v[q].y + v[q].z + v[q].w;
    }
    __shared__ float red[8];
    for (int o = 16; o; o >>= 1) s += __shfl_down_sync(0xffffffffu, s, o);
    if ((threadIdx.x & 31) == 0) red[threadIdx.x >> 5] = s;
    __syncthreads();
    if (threadIdx.x == 0) {
        float tt = 0.f;
#pragma unroll
        for (int q = 0; q < 8; q++) tt += red[q];
        red[0] = tt;
    }
    __syncthreads();
    float inv = 1.f / (red[0] + 1e-8f);
    size_t base = ((size_t)t * NN + i) * NN;
#pragma unroll
    for (int q = 0; q < 2; q++) {
        int j0 = (threadIdx.x + q * 256) * 4;
        *reinterpret_cast<__half2*>(&g_Gh[base + j0]) =
            __floats2half2_rn(v[q].x * inv, v[q].y * inv);
        *reinterpret_cast<__half2*>(&g_Gh[base + j0 + 2]) =
            __floats2half2_rn(v[q].z * inv, v[q].w * inv);
    }
}

// -------------------------------------------------------------------------
// Persistent fused 3-phase GEMM (grid GRID_P, strided tile loop):
//   phase 0: G2 = G*G    -> g_done[0][t]
//   phase 1: G3 = G2*G   -> g_done[1][t]   (waits g_done[0][t]==256)
//   phase 2: R  = Q*G3 + a2 G2 + a1 G + a0 I -> g_acc  (waits g_done[1][t])
// Next tile's first two stages prefetched under the current epilogue.
// -------------------------------------------------------------------------
__global__ __launch_bounds__(128, 2) void gemm_persistent_kernel() {
    extern __shared__ unsigned char dsm_raw[];
    uint32_t dsm = (uint32_t)__cvta_generic_to_shared(dsm_raw);
    uint32_t smem_base = (dsm + 1023) & ~1023u;
    __shared__ int s_ready;

    int tid = threadIdx.x;
    int l = tid & 31, wid = tid >> 5;
    int wm = wid & 1, wn = wid >> 1;

    uint32_t xorv  = (uint32_t)((l & 7) << 4);
    uint32_t a_row = (uint32_t)(wm * 64 + (l & 15));
    uint32_t a_kb  = (uint32_t)((l >> 4) << 4);
    uint32_t b_k0  = (uint32_t)(l & 15);
    uint32_t b_nb  = (uint32_t)(wn * 128 + ((l >> 4) << 4));

    // cooperative stage load for an arbitrary tile
    auto load_stage = [&](const TileInfo& ti, int s, int kk) {
        uint32_t stA = smem_base + s * STAGE_BYTES;
        uint32_t stB = stA + BM * 128;
        const __half* Ab = ti.A + ti.baseT + (size_t)ti.m0 * NN + kk;
        const __half* Bb = ti.B + ti.baseT + (size_t)kk * NN + ti.n0;
#pragma unroll
        for (int q = 0; q < 8; q++) {
            int id = tid + q * 128;
            int row = id >> 3, kc = id & 7;
            cpasync16(stA + ((uint32_t)(row << 7) + (((uint32_t)(kc << 4)) ^ ((uint32_t)(row & 7) << 4))),
                      Ab + (size_t)row * NN + kc * 8);
        }
#pragma unroll
        for (int q = 0; q < 8; q++) {
            int id = tid + q * 128;
            int k = id >> 4, nc = id & 15;
            cpasync16(stB + ((uint32_t)(k << 8) + (((uint32_t)(nc << 4)) ^ ((uint32_t)(k & 7) << 4))),
                      Bb + (size_t)k * NN + nc * 8);
        }
        asm volatile("cp.async.commit_group;\n");
    };

    int sbase = 0;
    int pf = 0;   // next tile already prefetched into (sbase) / (sbase+1)%3?

#pragma unroll 1
    for (int idx = blockIdx.x; idx < TOT_TILES; idx += GRID_P) {
        TileInfo ti = decode_tile(idx);

        if (!pf) {
            if (tid == 0 && ti.phase > 0) {
                volatile int* flag = &g_done[ti.phase - 1][ti.t];
                while (atomicAdd((int*)flag, 0) < TILES_PER_T) __nanosleep(128);
                __threadfence();
            }
            __syncthreads();
            load_stage(ti, sbase, 0);
            load_stage(ti, (sbase + 1) % 3, BK);
        }

        float cf[4][8][4];
#pragma unroll
        for (int mt = 0; mt < 4; mt++)
#pragma unroll
            for (int nf = 0; nf < 8; nf++)
#pragma unroll
                for (int e = 0; e < 4; e++) cf[mt][nf][e] = 0.f;

        uint32_t af[2][4][4], bf[2][4][4];

        auto load_frags = [&](int buf, uint32_t stA, uint32_t stB, int ks) {
#pragma unroll
            for (int mt = 0; mt < 4; mt++)
                ldsm4(af[buf][mt], stA + ((a_row + mt * 16) << 7) + ((a_kb + ks * 32) ^ xorv));
#pragma unroll
            for (int np = 0; np < 4; np++)
                ldsm4t(bf[buf][np], stB + ((b_k0 + ks * 16) << 8) + ((b_nb + np * 32) ^ xorv));
        };
        auto mma_frags = [&](int buf) {
#pragma unroll
            for (int mt = 0; mt < 4; mt++)
#pragma unroll
                for (int np = 0; np < 4; np++) {
                    mma16816(cf[mt][np * 2],     af[buf][mt], bf[buf][np][0], bf[buf][np][1]);
                    mma16816(cf[mt][np * 2 + 1], af[buf][mt], bf[buf][np][2], bf[buf][np][3]);
                }
        };

#pragma unroll 1
        for (int ch = 0; ch < KCH; ch++) {
            if (ch + 1 < KCH) asm volatile("cp.async.wait_group 1;\n");
            else              asm volatile("cp.async.wait_group 0;\n");
            __syncthreads();

            uint32_t stA = smem_base + ((sbase + ch) % 3) * STAGE_BYTES;
            uint32_t stB = stA + BM * 128;

            load_frags(0, stA, stB, 0);
            load_frags(1, stA, stB, 1);
            mma_frags(0);
            if (ch + 2 < KCH) {
                load_stage(ti, (sbase + ch + 2) % 3, (ch + 2) * BK);
            } else if (ch == KCH - 2) {
                // non-blocking dep probe for next tile (result read after ch31 sync)
                if (tid == 0) {
                    int idx2 = idx + GRID_P;
                    int rdy = 0;
                    if (idx2 < TOT_TILES) {
                        int ph2 = idx2 / TILES_PER_PHASE;
                        int t2 = (idx2 - ph2 * TILES_PER_PHASE) / TILES_PER_T;
                        if (ph2 == 0) rdy = 1;
                        else if (atomicAdd(&g_done[ph2 - 1][t2], 0) >= TILES_PER_T) {
                            __threadfence();
                            rdy = 1;
                        }
                    }
                    s_ready = rdy;
                }
            } else {
                // ch == KCH-1: prefetch next tile's first two stages if ready
                if (s_ready) {
                    TileInfo tn = decode_tile(idx + GRID_P);
                    load_stage(tn, (sbase + 2) % 3, 0);
                    load_stage(tn, sbase, BK);
                }
            }
            load_frags(0, stA, stB, 2);
            mma_frags(1);
            load_frags(1, stA, stB, 3);
            mma_frags(0);
            mma_frags(1);
        }
        __syncthreads();
        pf = s_ready;

        // ---- epilogue: 4 sub-chunks of 32 rows, staged through the one
        // stage region the prefetch never touches: (sbase+1)%3 ----
        float* stg = reinterpret_cast<float*>(
            dsm_raw + (smem_base + ((sbase + 1) % 3) * STAGE_BYTES - dsm));

        float a0c = g_coef[ti.t][0], a1c = g_coef[ti.t][1], a2c = g_coef[ti.t][2];
        float a3c = g_coef[ti.t][3], a4c = g_coef[ti.t][4], a5c = g_coef[ti.t][5];

#pragma unroll 1
        for (int mt = 0; mt < 4; mt++) {
            int lr0 = wm * 16 + (l >> 2);
#pragma unroll
            for (int nf = 0; nf < 8; nf++) {
                int col = wn * 64 + nf * 8 + (l & 3) * 2;
                stg[lr0 * 132 + col]           = cf[mt][nf][0];
                stg[lr0 * 132 + col + 1]       = cf[mt][nf][1];
                stg[(lr0 + 8) * 132 + col]     = cf[mt][nf][2];
                stg[(lr0 + 8) * 132 + col + 1] = cf[mt][nf][3];
            }
            __syncthreads();

#pragma unroll 1
            for (int p = 0; p < 8; p++) {
                int lr = p * 4 + (tid >> 5);
                int col4 = (tid & 31) * 4;
                int gi = ti.m0 + (lr >> 4) * 64 + mt * 16 + (lr & 15);
                int gj = ti.n0 + col4;
                int dj = gi - gj;
                size_t o = ti.baseT + (size_t)gi * NN + gj;
                float v0 = stg[lr * 132 + col4],     v1 = stg[lr * 132 + col4 + 1];
                float v2 = stg[lr * 132 + col4 + 2], v3 = stg[lr * 132 + col4 + 3];

                if (ti.phase == 0) {
                    uint2 gv = *reinterpret_cast<const uint2*>(g_Gh + o);
                    __half2 g01 = *reinterpret_cast<__half2*>(&gv.x);
                    __half2 g23 = *reinterpret_cast<__half2*>(&gv.y);
                    float q0 = a5c * v0 + a4c * __low2float(g01)  + (dj == 0 ? a3c : 0.f);
                    float q1 = a5c * v1 + a4c * __high2float(g01) + (dj == 1 ? a3c : 0.f);
                    float q2 = a5c * v2 + a4c * __low2float(g23)  + (dj == 2 ? a3c : 0.f);
                    float q3 = a5c * v3 + a4c * __high2float(g23) + (dj == 3 ? a3c : 0.f);
                    union { uint2 u; __half2 h[2]; } pk, qk;
                    pk.h[0] = __floats2half2_rn(v0, v1); pk.h[1] = __floats2half2_rn(v2, v3);
                    qk.h[0] = __floats2half2_rn(q0, q1); qk.h[1] = __floats2half2_rn(q2, q3);
                    *reinterpret_cast<uint2*>(g_G2h + o) = pk.u;
                    *reinterpret_cast<uint2*>(g_Qh + o)  = qk.u;
                } else if (ti.phase == 1) {
                    union { uint2 u; __half2 h[2]; } pk;
                    pk.h[0] = __floats2half2_rn(v0, v1); pk.h[1] = __floats2half2_rn(v2, v3);
                    *reinterpret_cast<uint2*>(g_G3h + o) = pk.u;
                } else {
                    uint2 gv = *reinterpret_cast<const uint2*>(g_Gh + o);
                    uint2 g2 = *reinterpret_cast<const uint2*>(g_G2h + o);
                    __half2 g01 = *reinterpret_cast<__half2*>(&gv.x);
                    __half2 g23 = *reinterpret_cast<__half2*>(&gv.y);
                    __half2 h01 = *reinterpret_cast<__half2*>(&g2.x);
                    __half2 h23 = *reinterpret_cast<__half2*>(&g2.y);
                    float4 rr;
                    rr.x = v0 + a2c * __low2float(h01)  + a1c * __low2float(g01)  + (dj == 0 ? a0c : 0.f);
                    rr.y = v1 + a2c * __high2float(h01) + a1c * __high2float(g01) + (dj == 1 ? a0c : 0.f);
                    rr.z = v2 + a2c * __low2float(h23)  + a1c * __low2float(g23)  + (dj == 2 ? a0c : 0.f);
                    rr.w = v3 + a2c * __high2float(h23) + a1c * __high2float(g23) + (dj == 3 ? a0c : 0.f);
                    *reinterpret_cast<float4*>(g_acc + o) = rr;
                }
            }
            __syncthreads();
        }

        if (ti.phase < 2) {
            if (tid == 0) {
                __threadfence();
                atomicAdd(&g_done[ti.phase][ti.t], 1);
            }
        }

        sbase = (sbase + 2) % 3;   // 32 chunks consumed: +32 mod 3 = +2
    }
}

// -------------------------------------------------------------------------
// LayerNorm over acc rows -> out[i][t][j]. t iterated in REVERSE so the
// most-recently-written (L2-hot) acc slices are read first.
// -------------------------------------------------------------------------
__global__ __launch_bounds__(256) void ln_kernel(const float* __restrict__ gamma,
                                                 const float* __restrict__ beta,
                                                 float* __restrict__ out) {
    int row = blockIdx.x;
    int tr = row / NN;
    int t = NT - 1 - tr;
    int i = row - tr * NN;
    const float4* a = reinterpret_cast<const float4*>(g_acc + ((size_t)t * NN + i) * NN);

    float4 v[2];
    float s = 0.f, ss = 0.f;
#pragma unroll
    for (int q = 0; q < 2; q++) {
        v[q] = a[threadIdx.x + q * 256];
        s  += v[q].x + v[q].y + v[q].z + v[q].w;
        ss += v[q].x * v[q].x + v[q].y * v[q].y + v[q].z * v[q].z + v[q].w * v[q].w;
    }
    __shared__ float rs[8], rss[8];
    for (int o = 16; o; o >>= 1) {
        s  += __shfl_down_sync(0xffffffffu, s, o);
        ss += __shfl_down_sync(0xffffffffu, ss, o);
    }
    if ((threadIdx.x & 31) == 0) { rs[threadIdx.x >> 5] = s; rss[threadIdx.x >> 5] = ss; }
    __syncthreads();
    if (threadIdx.x == 0) {
        float t1 = 0.f, t2 = 0.f;
#pragma unroll
        for (int q = 0; q < 8; q++) { t1 += rs[q]; t2 += rss[q]; }
        rs[0] = t1; rss[0] = t2;
    }
    __syncthreads();
    float mu = rs[0] * (1.f / NN);
    float var = rss[0] * (1.f / NN) - mu * mu;
    float rstd = rsqrtf(var + LN_EPS);

    float4* o = reinterpret_cast<float4*>(out + ((size_t)i * NT + t) * NN);
    const float4* gm = reinterpret_cast<const float4*>(gamma);
    const float4* bt = reinterpret_cast<const float4*>(beta);
#pragma unroll
    for (int q = 0; q < 2; q++) {
        int idx = threadIdx.x + q * 256;
        float4 g = gm[idx], b = bt[idx];
        float4 r;
        r.x = (v[q].x - mu) * rstd * g.x + b.x;
        r.y = (v[q].y - mu) * rstd * g.y + b.y;
        r.z = (v[q].z - mu) * rstd * g.z + b.z;
        r.w = (v[q].w - mu) * rstd * g.w + b.w;
        o[idx] = r;
    }
}

extern "C" void kernel_launch(void* const* d_in, const int* in_sizes, int n_in,
                              void* d_out, int out_size) {
    const float* x      = (const float*)d_in[0];
    const float* weight = (const float*)d_in[1];
    const float* gamma  = (const float*)d_in[2];
    const float* beta   = (const float*)d_in[3];
    float* out = (float*)d_out;

    cudaFuncSetAttribute(gemm_persistent_kernel,
                         cudaFuncAttributeMaxDynamicSharedMemorySize, SMEM_DYN);

    prep_kernel<<<NT * NN, 256>>>(x, weight);
    gemm_persistent_kernel<<<GRID_P, 128, SMEM_DYN>>>();
    ln_kernel<<<NT * NN, 256>>>(gamma, beta, out);
}

// round 17
// speedup vs baseline: 7.0460x; 7.0460x over previous
#include <cuda_runtime.h>
#include <cuda_fp16.h>
#include <cstdint>

#define NN 2048
#define NT 10
#define KK 5
constexpr float LN_EPS = 1e-5f;

// GEMM tiling: CTA 128x128, BK=64, 4 warps (2x2), warp tile 64x64, 3 stages
// 2 CTAs/SM. 3 GEMM phases fused in one launch with coarse per-(phase,t)
// flag dependencies. prep/LN dedicated high-occupancy kernels.
#define BM 128
#define BN 128
#define BK 64
#define KCH (NN / BK)                          // 32
#define STAGE_BYTES (BM * 128 + BK * 256)      // A 16KB + B 16KB = 32KB
#define SMEM_DYN (3 * STAGE_BYTES + 1024)      // 99328
#define TILES_PER_T 256                        // 16x16
#define TILES_PER_PHASE (NT * TILES_PER_T)     // 2560

// Scratch (__device__ globals; allocation-free rule)
__device__ __half g_Gh [(size_t)NT * NN * NN];  // G_norm
__device__ __half g_G2h[(size_t)NT * NN * NN];  // G^2
__device__ __half g_G3h[(size_t)NT * NN * NN];  // G^3
__device__ __half g_Qh [(size_t)NT * NN * NN];  // Q = a5 G^2 + a4 G + a3 I
__device__ float  g_acc[(size_t)NT * NN * NN];  // pre-LN accumulator (fp32)
__device__ float  g_coef[NT][6];
__device__ int    g_done[2][NT];                // tile-completion counters

__device__ __forceinline__ float clip01(float v) { return fminf(fmaxf(v, 0.f), 1.f); }

__device__ __forceinline__ void cpasync16(uint32_t s, const void* g) {
    asm volatile("cp.async.cg.shared.global [%0], [%1], 16;\n" :: "r"(s), "l"(g));
}
__device__ __forceinline__ void ldsm4(uint32_t* r, uint32_t addr) {
    asm volatile("ldmatrix.sync.aligned.m8n8.x4.shared.b16 {%0,%1,%2,%3}, [%4];"
                 : "=r"(r[0]), "=r"(r[1]), "=r"(r[2]), "=r"(r[3]) : "r"(addr));
}
__device__ __forceinline__ void ldsm4t(uint32_t* r, uint32_t addr) {
    asm volatile("ldmatrix.sync.aligned.m8n8.x4.trans.shared.b16 {%0,%1,%2,%3}, [%4];"
                 : "=r"(r[0]), "=r"(r[1]), "=r"(r[2]), "=r"(r[3]) : "r"(addr));
}
__device__ __forceinline__ void mma16816(float* c, const uint32_t* a,
                                         uint32_t b0, uint32_t b1) {
    asm volatile("mma.sync.aligned.m16n8k16.row.col.f32.f16.f16.f32 "
                 "{%0,%1,%2,%3}, {%4,%5,%6,%7}, {%8,%9}, {%0,%1,%2,%3};"
                 : "+f"(c[0]), "+f"(c[1]), "+f"(c[2]), "+f"(c[3])
                 : "r"(a[0]), "r"(a[1]), "r"(a[2]), "r"(a[3]), "r"(b0), "r"(b1));
}

// -------------------------------------------------------------------------
// prep: per (t,i) row — degree + row-normalize -> g_Gh (fp16).
// Block 0 also computes the polynomial coefficients and zeroes the
// dependency counters (visible to the fused launch via the stream boundary).
// -------------------------------------------------------------------------
__global__ __launch_bounds__(256) void prep_kernel(const float* __restrict__ x,
                                                   const float* __restrict__ w) {
    if (blockIdx.x == 0) {
        int id = threadIdx.x;
        if (id < 2 * NT) ((int*)g_done)[id] = 0;
        if (id < NT) {
            int t = id;
            float c[6] = {1.f, 0.f, 0.f, 0.f, 0.f, 0.f};
            float a[6] = {0.f, 0.f, 0.f, 0.f, 0.f, 0.f};
            for (int k = 0; k < KK; k++) {
                float wk = clip01(w[t * KK + k]);
                float nc[6];
                nc[0] = 1.f - wk;
#pragma unroll
                for (int m = 1; m < 6; m++) nc[m] = wk * c[m - 1];
#pragma unroll
                for (int m = 0; m < 6; m++) { c[m] = nc[m]; a[m] += nc[m]; }
            }
#pragma unroll
            for (int m = 0; m < 6; m++) g_coef[t][m] = a[m];
        }
    }

    int row = blockIdx.x;
    int t = row / NN, i = row - t * NN;
    const float4* xr = reinterpret_cast<const float4*>(x + ((size_t)i * NT + t) * NN);

    float4 v[2];
    float s = 0.f;
#pragma unroll
    for (int q = 0; q < 2; q++) {
        v[q] = xr[threadIdx.x + q * 256];
        s += v[q].x + v[q].y + v[q].z + v[q].w;
    }
    __shared__ float red[8];
    for (int o = 16; o; o >>= 1) s += __shfl_down_sync(0xffffffffu, s, o);
    if ((threadIdx.x & 31) == 0) red[threadIdx.x >> 5] = s;
    __syncthreads();
    if (threadIdx.x == 0) {
        float tt = 0.f;
#pragma unroll
        for (int q = 0; q < 8; q++) tt += red[q];
        red[0] = tt;
    }
    __syncthreads();
    float inv = 1.f / (red[0] + 1e-8f);
    size_t base = ((size_t)t * NN + i) * NN;
#pragma unroll
    for (int q = 0; q < 2; q++) {
        int j0 = (threadIdx.x + q * 256) * 4;
        *reinterpret_cast<__half2*>(&g_Gh[base + j0]) =
            __floats2half2_rn(v[q].x * inv, v[q].y * inv);
        *reinterpret_cast<__half2*>(&g_Gh[base + j0 + 2]) =
            __floats2half2_rn(v[q].z * inv, v[q].w * inv);
    }
}

// -------------------------------------------------------------------------
// Fused 3-phase GEMM, one launch (grid 3*2560):
//   phase 0: G2 = G*G    (writes G2h, Qh)       -> g_done[0][t]
//   phase 1: G3 = G2*G   (writes G3h)           -> g_done[1][t]
//   phase 2: R  = Q*G3   (writes g_acc = R + a2 G2 + a1 G + a0 I)
// Consumers spin on the producer phase's per-t tile counter.
// -------------------------------------------------------------------------
__global__ __launch_bounds__(128, 2) void gemm_fused_kernel() {
    extern __shared__ unsigned char dsm_raw[];
    uint32_t dsm = (uint32_t)__cvta_generic_to_shared(dsm_raw);
    uint32_t smem_base = (dsm + 1023) & ~1023u;
    float* stg = reinterpret_cast<float*>(dsm_raw + (smem_base - dsm));

    int tid = threadIdx.x;
    int l = tid & 31, wid = tid >> 5;
    int wm = wid & 1, wn = wid >> 1;     // 2x2 warp grid

    int bid = blockIdx.x;
    int phase = bid / TILES_PER_PHASE;
    int rem = bid - phase * TILES_PER_PHASE;
    int t = rem / TILES_PER_T;
    int tile = rem - t * TILES_PER_T;
    int m0 = (tile >> 4) * BM;
    int n0 = (tile & 15) * BN;
    size_t baseT = (size_t)t * NN * NN;

    // wait for producer phase (per-t granularity)
    if (phase > 0) {
        if (tid == 0) {
            volatile int* flag = &g_done[phase - 1][t];
            while (atomicAdd((int*)flag, 0) < TILES_PER_T) __nanosleep(128);
            __threadfence();
        }
        __syncthreads();
    }

    const __half *A, *B;
    if (phase == 0)      { A = g_Gh;  B = g_Gh;  }
    else if (phase == 1) { A = g_G2h; B = g_Gh;  }
    else                 { A = g_Qh;  B = g_G3h; }

    float cf[4][8][4];
#pragma unroll
    for (int mt = 0; mt < 4; mt++)
#pragma unroll
        for (int nf = 0; nf < 8; nf++)
#pragma unroll
            for (int e = 0; e < 4; e++) cf[mt][nf][e] = 0.f;

    uint32_t xorv  = (uint32_t)((l & 7) << 4);
    uint32_t a_row = (uint32_t)(wm * 64 + (l & 15));
    uint32_t a_kb  = (uint32_t)((l >> 4) << 4);
    uint32_t b_k0  = (uint32_t)(l & 15);
    uint32_t b_nb  = (uint32_t)(wn * 128 + ((l >> 4) << 4));   // bytes

    auto load_stage = [&](int s, int kk) {
        uint32_t stA = smem_base + s * STAGE_BYTES;
        uint32_t stB = stA + BM * 128;
        const __half* Ab = A + baseT + (size_t)m0 * NN + kk;
        const __half* Bb = B + baseT + (size_t)kk * NN + n0;
#pragma unroll
        for (int q = 0; q < 8; q++) {            // A: 1024 16B chunks
            int id = tid + q * 128;
            int row = id >> 3, kc = id & 7;
            cpasync16(stA + ((uint32_t)(row << 7) + (((uint32_t)(kc << 4)) ^ ((uint32_t)(row & 7) << 4))),
                      Ab + (size_t)row * NN + kc * 8);
        }
#pragma unroll
        for (int q = 0; q < 8; q++) {            // B: 1024 16B chunks
            int id = tid + q * 128;
            int k = id >> 4, nc = id & 15;
            cpasync16(stB + ((uint32_t)(k << 8) + (((uint32_t)(nc << 4)) ^ ((uint32_t)(k & 7) << 4))),
                      Bb + (size_t)k * NN + nc * 8);
        }
        asm volatile("cp.async.commit_group;\n");
    };

    uint32_t af[2][4][4], bf[2][4][4];

    auto load_frags = [&](int buf, uint32_t stA, uint32_t stB, int ks) {
#pragma unroll
        for (int mt = 0; mt < 4; mt++)
            ldsm4(af[buf][mt], stA + ((a_row + mt * 16) << 7) + ((a_kb + ks * 32) ^ xorv));
#pragma unroll
        for (int np = 0; np < 4; np++)
            ldsm4t(bf[buf][np], stB + ((b_k0 + ks * 16) << 8) + ((b_nb + np * 32) ^ xorv));
    };
    auto mma_frags = [&](int buf) {
#pragma unroll
        for (int mt = 0; mt < 4; mt++)
#pragma unroll
            for (int np = 0; np < 4; np++) {
                mma16816(cf[mt][np * 2],     af[buf][mt], bf[buf][np][0], bf[buf][np][1]);
                mma16816(cf[mt][np * 2 + 1], af[buf][mt], bf[buf][np][2], bf[buf][np][3]);
            }
    };

    load_stage(0, 0);
    load_stage(1, BK);

#pragma unroll 1
    for (int ch = 0; ch < KCH; ch++) {
        if (ch + 1 < KCH) asm volatile("cp.async.wait_group 1;\n");
        else              asm volatile("cp.async.wait_group 0;\n");
        __syncthreads();

        uint32_t stA = smem_base + (ch % 3) * STAGE_BYTES;
        uint32_t stB = stA + BM * 128;

        load_frags(0, stA, stB, 0);
        load_frags(1, stA, stB, 1);   // prefetch ks1
        mma_frags(0);                 // ks0
        if (ch + 2 < KCH) load_stage((ch + 2) % 3, (ch + 2) * BK);
        load_frags(0, stA, stB, 2);   // prefetch ks2
        mma_frags(1);                 // ks1
        load_frags(1, stA, stB, 3);   // prefetch ks3
        mma_frags(0);                 // ks2
        mma_frags(1);                 // ks3
    }
    __syncthreads();

    // stage accumulators through smem (stride 132 floats)
#pragma unroll
    for (int mt = 0; mt < 4; mt++) {
        int r0 = wm * 64 + mt * 16 + (l >> 2);
#pragma unroll
        for (int nf = 0; nf < 8; nf++) {
            int col = wn * 64 + nf * 8 + (l & 3) * 2;
            stg[r0 * 132 + col]           = cf[mt][nf][0];
            stg[r0 * 132 + col + 1]       = cf[mt][nf][1];
            stg[(r0 + 8) * 132 + col]     = cf[mt][nf][2];
            stg[(r0 + 8) * 132 + col + 1] = cf[mt][nf][3];
        }
    }
    __syncthreads();

    float a0c = g_coef[t][0], a1c = g_coef[t][1], a2c = g_coef[t][2];
    float a3c = g_coef[t][3], a4c = g_coef[t][4], a5c = g_coef[t][5];

#pragma unroll 1
    for (int pass = 0; pass < 32; pass++) {
        int r = pass * 4 + (tid >> 5);
        int col = (tid & 31) * 4;
        int gi = m0 + r;
        int dj = gi - (n0 + col);          // 0..3 => diagonal hit
        size_t o = baseT + (size_t)gi * NN + (n0 + col);
        float v0 = stg[r * 132 + col],     v1 = stg[r * 132 + col + 1];
        float v2 = stg[r * 132 + col + 2], v3 = stg[r * 132 + col + 3];

        if (phase == 0) {
            uint2 gv = *reinterpret_cast<const uint2*>(g_Gh + o);
            __half2 g01 = *reinterpret_cast<__half2*>(&gv.x);
            __half2 g23 = *reinterpret_cast<__half2*>(&gv.y);
            float q0 = a5c * v0 + a4c * __low2float(g01)  + (dj == 0 ? a3c : 0.f);
            float q1 = a5c * v1 + a4c * __high2float(g01) + (dj == 1 ? a3c : 0.f);
            float q2 = a5c * v2 + a4c * __low2float(g23)  + (dj == 2 ? a3c : 0.f);
            float q3 = a5c * v3 + a4c * __high2float(g23) + (dj == 3 ? a3c : 0.f);
            union { uint2 u; __half2 h[2]; } p, q;
            p.h[0] = __floats2half2_rn(v0, v1); p.h[1] = __floats2half2_rn(v2, v3);
            q.h[0] = __floats2half2_rn(q0, q1); q.h[1] = __floats2half2_rn(q2, q3);
            *reinterpret_cast<uint2*>(g_G2h + o) = p.u;
            *reinterpret_cast<uint2*>(g_Qh + o)  = q.u;
        } else if (phase == 1) {
            union { uint2 u; __half2 h[2]; } p;
            p.h[0] = __floats2half2_rn(v0, v1); p.h[1] = __floats2half2_rn(v2, v3);
            *reinterpret_cast<uint2*>(g_G3h + o) = p.u;
        } else {
            uint2 gv = *reinterpret_cast<const uint2*>(g_Gh + o);
            uint2 g2 = *reinterpret_cast<const uint2*>(g_G2h + o);
            __half2 g01 = *reinterpret_cast<__half2*>(&gv.x);
            __half2 g23 = *reinterpret_cast<__half2*>(&gv.y);
            __half2 h01 = *reinterpret_cast<__half2*>(&g2.x);
            __half2 h23 = *reinterpret_cast<__half2*>(&g2.y);
            float4 rr;
            rr.x = v0 + a2c * __low2float(h01)  + a1c * __low2float(g01)  + (dj == 0 ? a0c : 0.f);
            rr.y = v1 + a2c * __high2float(h01) + a1c * __high2float(g01) + (dj == 1 ? a0c : 0.f);
            rr.z = v2 + a2c * __low2float(h23)  + a1c * __low2float(g23)  + (dj == 2 ? a0c : 0.f);
            rr.w = v3 + a2c * __high2float(h23) + a1c * __high2float(g23) + (dj == 3 ? a0c : 0.f);
            *reinterpret_cast<float4*>(g_acc + o) = rr;
        }
    }

    // signal completion (phases 0 and 1 feed a consumer)
    if (phase < 2) {
        __syncthreads();
        if (tid == 0) {
            __threadfence();
            atomicAdd(&g_done[phase][t], 1);
        }
    }
}

// -------------------------------------------------------------------------
// LayerNorm over acc rows -> out[i][t][j]. t iterated in REVERSE so the
// most-recently-written (L2-hot) acc slices are read first.
// -------------------------------------------------------------------------
__global__ __launch_bounds__(256) void ln_kernel(const float* __restrict__ gamma,
                                                 const float* __restrict__ beta,
                                                 float* __restrict__ out) {
    int row = blockIdx.x;
    int tr = row / NN;
    int t = NT - 1 - tr;
    int i = row - tr * NN;
    const float4* a = reinterpret_cast<const float4*>(g_acc + ((size_t)t * NN + i) * NN);

    float4 v[2];
    float s = 0.f, ss = 0.f;
#pragma unroll
    for (int q = 0; q < 2; q++) {
        v[q] = a[threadIdx.x + q * 256];
        s  += v[q].x + v[q].y + v[q].z + v[q].w;
        ss += v[q].x * v[q].x + v[q].y * v[q].y + v[q].z * v[q].z + v[q].w * v[q].w;
    }
    __shared__ float rs[8], rss[8];
    for (int o = 16; o; o >>= 1) {
        s  += __shfl_down_sync(0xffffffffu, s, o);
        ss += __shfl_down_sync(0xffffffffu, ss, o);
    }
    if ((threadIdx.x & 31) == 0) { rs[threadIdx.x >> 5] = s; rss[threadIdx.x >> 5] = ss; }
    __syncthreads();
    if (threadIdx.x == 0) {
        float t1 = 0.f, t2 = 0.f;
#pragma unroll
        for (int q = 0; q < 8; q++) { t1 += rs[q]; t2 += rss[q]; }
        rs[0] = t1; rss[0] = t2;
    }
    __syncthreads();
    float mu = rs[0] * (1.f / NN);
    float var = rss[0] * (1.f / NN) - mu * mu;
    float rstd = rsqrtf(var + LN_EPS);

    float4* o = reinterpret_cast<float4*>(out + ((size_t)i * NT + t) * NN);
    const float4* gm = reinterpret_cast<const float4*>(gamma);
    const float4* bt = reinterpret_cast<const float4*>(beta);
#pragma unroll
    for (int q = 0; q < 2; q++) {
        int idx = threadIdx.x + q * 256;
        float4 g = gm[idx], b = bt[idx];
        float4 r;
        r.x = (v[q].x - mu) * rstd * g.x + b.x;
        r.y = (v[q].y - mu) * rstd * g.y + b.y;
        r.z = (v[q].z - mu) * rstd * g.z + b.z;
        r.w = (v[q].w - mu) * rstd * g.w + b.w;
        o[idx] = r;
    }
}

extern "C" void kernel_launch(void* const* d_in, const int* in_sizes, int n_in,
                              void* d_out, int out_size) {
    const float* x      = (const float*)d_in[0];
    const float* weight = (const float*)d_in[1];
    const float* gamma  = (const float*)d_in[2];
    const float* beta   = (const float*)d_in[3];
    float* out = (float*)d_out;

    cudaFuncSetAttribute(gemm_fused_kernel,
                         cudaFuncAttributeMaxDynamicSharedMemorySize, SMEM_DYN);

    prep_kernel<<<NT * NN, 256>>>(x, weight);
    gemm_fused_kernel<<<3 * TILES_PER_PHASE, 128, SMEM_DYN>>>();
    ln_kernel<<<NT * NN, 256>>>(gamma, beta, out);
}